// round 14
// baseline (speedup 1.0000x reference)
#include <cuda_runtime.h>
#include <math.h>

#define N_PATHS 2048
#define N_STEPS 512
#define N_FWD   40
#define DT_F    (1.0f/512.0f)
#define SHIFT_F 0.02f
// DT^-0.4 / Gamma(0.6) = 2^3.6 / 1.4891922488128176
#define SC_CONST 8.142489698f
// C = SC / Gamma(0.4)
#define C_CONST  (SC_CONST / 2.2181595437576885f)

// ---- sum-of-exponentials quadrature: g[k] ~= sum_m w_m lam_m^k for k >= K0 ----
#define M_SOE 32
#define HQ    1.0f
#define Y0_Q  (-29.5f)
#define K0    8
#define LCH   16
#define NCH   32

// ---------------- device scratch ----------------
__device__ float d_g[N_STEPS];
__device__ float d_s2[N_STEPS];
__device__ float d_vs[N_FWD];
__device__ float d_mu0[N_FWD];
__device__ float d_lam[M_SOE];
__device__ float d_wk[M_SOE];      // w_m * lam^K0
__device__ float d_lamL[M_SOE];    // lam^LCH

// ---------------- f32x2 packed helpers ----------------
__device__ __forceinline__ unsigned long long pack2(float a, float b) {
    unsigned long long r;
    asm("mov.b64 %0, {%1, %2};" : "=l"(r) : "f"(a), "f"(b));
    return r;
}
__device__ __forceinline__ void unpack2(unsigned long long v, float& a, float& b) {
    asm("mov.b64 {%0, %1}, %2;" : "=f"(a), "=f"(b) : "l"(v));
}
__device__ __forceinline__ unsigned long long fma2(unsigned long long a,
                                                   unsigned long long b,
                                                   unsigned long long c) {
    unsigned long long d;
    asm("fma.rn.f32x2 %0, %1, %2, %3;" : "=l"(d) : "l"(a), "l"(b), "l"(c));
    return d;
}

// ---------------- pre_a: taps (8 blocks) + SOE consts + per-n consts (block 8) ----
__global__ void pre_a(const float* __restrict__ F0,
                      const float* __restrict__ alphas,
                      const float* __restrict__ tau,
                      const float* __restrict__ Lam) {
    __shared__ float som[N_FWD];
    __shared__ float svs[N_FWD];
    const int b = blockIdx.x, tid = threadIdx.x;
    if (b < 8) {
        int t = b * 64 + tid;
        float w;
        if (t == 0) {
            w = 1.0f / 0.6f;
        } else {
            float tf = (float)t;
            w = powf(tf, 0.6f) * expm1f(0.6f * log1pf(1.0f / tf)) * (1.0f / 0.6f);
        }
        d_g[t] = w * SC_CONST;
    } else {
        if (tid < M_SOE) {
            float y = Y0_Q + (float)tid * HQ;
            float x = expf(y);
            float lam = expf(-x);
            float w = HQ * C_CONST * expf(-0.6f * y) * (-expm1f(-x));
            float l2 = lam * lam, l4 = l2 * l2, l8 = l4 * l4;
            d_lam[tid]  = lam;
            d_wk[tid]   = w * l8;       // K0 = 8
            d_lamL[tid] = l8 * l8;      // LCH = 16
        }
        if (tid < N_FWD) {
            float f0v = F0[tid];
            float vs  = alphas[tid] * sqrtf(fabsf(f0v + SHIFT_F));
            svs[tid]  = vs;
            d_vs[tid] = vs;
            som[tid]  = tau[tid] * vs / (1.0f + tau[tid] * f0v);
        }
        __syncthreads();
        if (tid < N_FWD) {
            float acc = 0.0f;
            #pragma unroll 8
            for (int m = 0; m < N_FWD; m++)
                acc += Lam[tid * N_FWD + m] * som[m];
            d_mu0[tid] = -svs[tid] * acc;
        }
    }
}

// ---------------- pre_b: prefix sum of g^2 ----------------
__global__ void pre_b() {
    const int t = threadIdx.x, lane = t & 31, w = t >> 5;
    float gv = d_g[t];
    float v = gv * gv;
    #pragma unroll
    for (int o = 1; o < 32; o <<= 1) {
        float nv = __shfl_up_sync(0xffffffffu, v, o);
        if (lane >= o) v += nv;
    }
    __shared__ float wsum[16];
    if (lane == 31) wsum[w] = v;
    __syncthreads();
    if (w == 0 && lane < 16) {
        float s = wsum[lane];
        #pragma unroll
        for (int o = 1; o < 16; o <<= 1) {
            float nv = __shfl_up_sync(0xffffu, s, o);
            if (lane >= o) s += nv;
        }
        wsum[lane] = s;
    }
    __syncthreads();
    d_s2[t] = v + ((w > 0) ? wsum[w - 1] : 0.0f);
}

// ---------------- fused kernel ----------------
#define PPB 2
#define FUSED_TPB 128
#define PH2_THREADS (PPB * N_FWD)

// dynamic smem layout (bytes)
#define OFF_SDZ   0                                        // float4[1024] 16384
#define OFF_SFBM  (OFF_SDZ + 16384)                        // float4[2*32*17] 17408 (padded)
#define OFF_V     (OFF_SFBM + 17408)                       // u64[2*2*32*33] 33792 (padded)
#define OFF_SS2   (OFF_V + 33792)                          // float[512] 2048
#define OFF_LAM   (OFF_SS2 + 2048)                         // float[32]
#define OFF_WK    (OFF_LAM + 128)
#define OFF_LAML  (OFF_WK + 128)
#define OFF_G     (OFF_LAML + 128)                         // float[8]
#define SMEM_BYTES (OFF_G + 32)                            // 70048

__global__ void __launch_bounds__(FUSED_TPB)
fused_kernel(const float4* __restrict__ dz,
             const float*  __restrict__ F0,
             const float*  __restrict__ rhos,
             const float*  __restrict__ nus,
             const float*  __restrict__ loadings,
             float* __restrict__ out) {
    extern __shared__ __align__(16) char smem_raw[];
    float4* sdz4  = (float4*)(smem_raw + OFF_SDZ);
    float4* sfbm4 = (float4*)(smem_raw + OFF_SFBM);
    unsigned long long* VU   = (unsigned long long*)(smem_raw + OFF_V);
    unsigned long long* sdzU = (unsigned long long*)(smem_raw + OFF_SDZ);
    unsigned long long* sfbU = (unsigned long long*)(smem_raw + OFF_SFBM);
    float* ss2   = (float*)(smem_raw + OFF_SS2);
    float* s_lam = (float*)(smem_raw + OFF_LAM);
    float* s_wk  = (float*)(smem_raw + OFF_WK);
    float* s_lamL= (float*)(smem_raw + OFF_LAML);
    float* s_g   = (float*)(smem_raw + OFF_G);

    const int tid   = threadIdx.x;
    const int pbase = blockIdx.x * PPB;

    for (int i = tid; i < PPB * N_STEPS; i += FUSED_TPB)
        sdz4[i] = dz[(size_t)pbase * N_STEPS + i];
    for (int i = tid; i < N_STEPS; i += FUSED_TPB)
        ss2[i] = d_s2[i];
    if (tid < M_SOE) {
        s_lam[tid]  = d_lam[tid];
        s_wk[tid]   = d_wk[tid];
        s_lamL[tid] = d_lamL[tid];
    }
    if (tid < K0) s_g[tid] = d_g[tid];
    __syncthreads();

    // thread map for conv passes: chunk c, channel-pair dp, path q
    const int c  = tid & 31;
    const int dp = (tid >> 5) & 1;
    const int q  = tid >> 6;
    const int tb = c * LCH;
    const int vbase = ((q * 2 + dp) * M_SOE) * 33;

    // delayed stream u[t] = dz[t - K0] for t in chunk, cached in regs
    unsigned long long dzc[LCH];
    #pragma unroll
    for (int i = 0; i < LCH; i++) {
        int gt = tb + i - K0;
        dzc[i] = (gt >= 0) ? sdzU[(q * N_STEPS + gt) * 2 + dp] : 0ull;
    }

    // ---- pass 1: per-chunk local state sums V (4 modes in flight for ILP) ----
    #pragma unroll 1
    for (int m = 0; m < M_SOE; m += 4) {
        unsigned long long l0 = pack2(s_lam[m + 0], s_lam[m + 0]);
        unsigned long long l1 = pack2(s_lam[m + 1], s_lam[m + 1]);
        unsigned long long l2 = pack2(s_lam[m + 2], s_lam[m + 2]);
        unsigned long long l3 = pack2(s_lam[m + 3], s_lam[m + 3]);
        unsigned long long S0 = 0ull, S1 = 0ull, S2 = 0ull, S3 = 0ull;
        #pragma unroll
        for (int i = 0; i < LCH; i++) {
            S0 = fma2(l0, S0, dzc[i]);
            S1 = fma2(l1, S1, dzc[i]);
            S2 = fma2(l2, S2, dzc[i]);
            S3 = fma2(l3, S3, dzc[i]);
        }
        VU[vbase + (m + 0) * 33 + c] = S0;
        VU[vbase + (m + 1) * 33 + c] = S1;
        VU[vbase + (m + 2) * 33 + c] = S2;
        VU[vbase + (m + 3) * 33 + c] = S3;
    }
    __syncthreads();

    // ---- pass 2: sequential carry propagation across chunks (remapped threads) ----
    {
        const int m2  = tid & 31;
        const int dp2 = (tid >> 5) & 1;
        const int q2  = tid >> 6;
        float ll = s_lamL[m2];
        unsigned long long lamL2 = pack2(ll, ll);
        unsigned long long run = 0ull;
        const int base = ((q2 * 2 + dp2) * M_SOE + m2) * 33;
        #pragma unroll 4
        for (int c2 = 0; c2 < NCH; c2++) {
            unsigned long long v = VU[base + c2];
            VU[base + c2] = run;          // now holds carry-in state for chunk c2
            run = fma2(lamL2, run, v);
        }
    }
    __syncthreads();

    // ---- pass 3: near field + mode replay (2 modes in flight), emit fbm ----
    {
        unsigned long long nc[K0];
        #pragma unroll
        for (int j = 0; j < K0; j++)
            nc[j] = sdzU[(q * N_STEPS + tb + K0 + j) * 2 + dp];

        unsigned long long F[LCH];
        #pragma unroll
        for (int i = 0; i < LCH; i++) {
            unsigned long long acc = 0ull;
            #pragma unroll
            for (int k = 0; k < K0; k++) {
                float gv = s_g[k];
                unsigned long long g2 = pack2(gv, gv);
                const int d = i - k;               // in [-7, 15]
                unsigned long long zv = (d <= 7) ? dzc[d + 8] : nc[d - 8];
                acc = fma2(g2, zv, acc);
            }
            F[i] = acc;
        }

        #pragma unroll 1
        for (int m = 0; m < M_SOE; m += 2) {
            unsigned long long la = pack2(s_lam[m + 0], s_lam[m + 0]);
            unsigned long long lb = pack2(s_lam[m + 1], s_lam[m + 1]);
            unsigned long long wa = pack2(s_wk[m + 0],  s_wk[m + 0]);
            unsigned long long wb = pack2(s_wk[m + 1],  s_wk[m + 1]);
            unsigned long long Sa = VU[vbase + (m + 0) * 33 + c];
            unsigned long long Sb = VU[vbase + (m + 1) * 33 + c];
            #pragma unroll
            for (int i = 0; i < LCH; i++) {
                Sa = fma2(la, Sa, dzc[i]);
                Sb = fma2(lb, Sb, dzc[i]);
                F[i] = fma2(wa, Sa, F[i]);
                F[i] = fma2(wb, Sb, F[i]);
            }
        }

        #pragma unroll
        for (int i = 0; i < LCH; i++)
            sfbU[(q * (NCH * 17) + c * 17 + i) * 2 + dp] = F[i];
    }
    __syncthreads();

    // ---- phase 2: mix / exp / dF / cumsum / store (R10 form) ----
    if (tid < PH2_THREADS) {
        const int qq = tid / N_FWD;
        const int n  = tid - qq * N_FWD;
        const int p  = pbase + qq;

        const float rho = rhos[n];
        const float nu  = nus[n];
        const float sq  = sqrtf(fmaxf(1.0f - rho * rho, 0.0f));
        const float l0  = loadings[n * 3 + 0];
        const float l1  = loadings[n * 3 + 1];
        const float l2  = loadings[n * 3 + 2];
        const float vs   = d_vs[n];
        const float muDT = d_mu0[n] * DT_F;
        const float cvar = 0.5f * nu * nu * DT_F;
        const float f0   = F0[n];

        float* op = out + (size_t)p * (N_STEPS + 1) * N_FWD + n;

        float acc = f0;
        __stcs(op, f0);
        op += N_FWD;

        for (int t = 0; t < N_STEPS; t++) {
            const int cc = t >> 4, ii = t & 15;
            float4 f = sfbm4[qq * (NCH * 17) + cc * 17 + ii];
            float4 z = sdz4[qq * N_STEPS + t];
            float fbm_curve = f.x * l0 + f.y * l1 + f.z * l2;
            float fbm = rho * fbm_curve + sq * f.w;
            float wr  = z.x * l0 + z.y * l1 + z.z * l2;
            float u   = __expf(nu * fbm - cvar * ss2[t]);
            acc += muDT * (u * u) + wr * (u * vs);
            __stcs(op, acc);
            op += N_FWD;
        }
    }
}

// ---------------- launcher ----------------
extern "C" void kernel_launch(void* const* d_in, const int* in_sizes, int n_in,
                              void* d_out, int out_size) {
    const float* dz       = (const float*)d_in[0];
    const float* F0       = (const float*)d_in[1];
    const float* alphas   = (const float*)d_in[2];
    const float* rhos     = (const float*)d_in[3];
    const float* nus      = (const float*)d_in[4];
    const float* tau      = (const float*)d_in[5];
    const float* loadings = (const float*)d_in[6];
    const float* Lam      = (const float*)d_in[7];
    float* out = (float*)d_out;

    cudaFuncSetAttribute(fused_kernel,
                         cudaFuncAttributeMaxDynamicSharedMemorySize, SMEM_BYTES);

    pre_a<<<9, 64>>>(F0, alphas, tau, Lam);
    pre_b<<<1, N_STEPS>>>();
    fused_kernel<<<N_PATHS / PPB, FUSED_TPB, SMEM_BYTES>>>(
        (const float4*)dz, F0, rhos, nus, loadings, out);
}

// round 15
// speedup vs baseline: 1.1817x; 1.1817x over previous
#include <cuda_runtime.h>
#include <math.h>

#define N_PATHS 2048
#define N_STEPS 512
#define N_FWD   40
#define DT_F    (1.0f/512.0f)
#define SHIFT_F 0.02f
// DT^-0.4 / Gamma(0.6) = 2^3.6 / 1.4891922488128176
#define SC_CONST 8.142489698f
// C = SC / Gamma(0.4)
#define C_CONST  (SC_CONST / 2.2181595437576885f)

// ---- sum-of-exponentials quadrature: g[k] ~= sum_m w_m lam_m^k for k >= K0 ----
#define M_SOE 32
#define HQ    1.0f
#define Y0_Q  (-29.5f)
#define K0    8
#define LCH   16
#define NCH   32

// ---------------- device scratch ----------------
__device__ float d_g[N_STEPS];
__device__ float d_vs[N_FWD];
__device__ float d_mu0[N_FWD];
__device__ float d_lam[M_SOE];
__device__ float d_wk[M_SOE];      // w_m * lam^K0
__device__ float d_lamL[M_SOE];    // lam^LCH

// ---------------- f32x2 packed helpers ----------------
__device__ __forceinline__ unsigned long long pack2(float a, float b) {
    unsigned long long r;
    asm("mov.b64 %0, {%1, %2};" : "=l"(r) : "f"(a), "f"(b));
    return r;
}
__device__ __forceinline__ void unpack2(unsigned long long v, float& a, float& b) {
    asm("mov.b64 {%0, %1}, %2;" : "=f"(a), "=f"(b) : "l"(v));
}
__device__ __forceinline__ unsigned long long fma2(unsigned long long a,
                                                   unsigned long long b,
                                                   unsigned long long c) {
    unsigned long long d;
    asm("fma.rn.f32x2 %0, %1, %2, %3;" : "=l"(d) : "l"(a), "l"(b), "l"(c));
    return d;
}

// ---------------- pre_a: taps (8 blocks) + SOE consts + per-n consts (block 8) ----
__global__ void pre_a(const float* __restrict__ F0,
                      const float* __restrict__ alphas,
                      const float* __restrict__ tau,
                      const float* __restrict__ Lam) {
    __shared__ float som[N_FWD];
    __shared__ float svs[N_FWD];
    const int b = blockIdx.x, tid = threadIdx.x;
    if (b < 8) {
        int t = b * 64 + tid;
        float w;
        if (t == 0) {
            w = 1.0f / 0.6f;
        } else {
            float tf = (float)t;
            w = powf(tf, 0.6f) * expm1f(0.6f * log1pf(1.0f / tf)) * (1.0f / 0.6f);
        }
        d_g[t] = w * SC_CONST;
    } else {
        if (tid < M_SOE) {
            float y = Y0_Q + (float)tid * HQ;
            float x = expf(y);
            float lam = expf(-x);
            float w = HQ * C_CONST * expf(-0.6f * y) * (-expm1f(-x));
            float l2 = lam * lam, l4 = l2 * l2, l8 = l4 * l4;
            d_lam[tid]  = lam;
            d_wk[tid]   = w * l8;       // K0 = 8
            d_lamL[tid] = l8 * l8;      // LCH = 16
        }
        if (tid < N_FWD) {
            float f0v = F0[tid];
            float vs  = alphas[tid] * sqrtf(fabsf(f0v + SHIFT_F));
            svs[tid]  = vs;
            d_vs[tid] = vs;
            som[tid]  = tau[tid] * vs / (1.0f + tau[tid] * f0v);
        }
        __syncthreads();
        if (tid < N_FWD) {
            float acc = 0.0f;
            #pragma unroll 8
            for (int m = 0; m < N_FWD; m++)
                acc += Lam[tid * N_FWD + m] * som[m];
            d_mu0[tid] = -svs[tid] * acc;
        }
    }
}

// ---------------- fused kernel ----------------
#define PPB 2
#define FUSED_TPB 128
#define PH2_THREADS (PPB * N_FWD)

// dynamic smem layout (bytes)
#define OFF_SDZ   0                                        // float4[1024] 16384
#define OFF_SFBM  (OFF_SDZ + 16384)                        // float4[2*32*17] 17408 (padded)
#define OFF_SS2   (OFF_SFBM + 17408)                       // float[512] 2048
#define OFF_LAM   (OFF_SS2 + 2048)                         // float[32]
#define OFF_WK    (OFF_LAM + 128)
#define OFF_LAML  (OFF_WK + 128)
#define OFF_G     (OFF_LAML + 128)                         // float[8]
#define OFF_WTOT  (OFF_G + 32)                             // float[4]
#define SMEM_BYTES (OFF_WTOT + 16)                         // ~36.2KB -> 5 blocks/SM

__global__ void __launch_bounds__(FUSED_TPB, 5)
fused_kernel(const float4* __restrict__ dz,
             const float*  __restrict__ F0,
             const float*  __restrict__ rhos,
             const float*  __restrict__ nus,
             const float*  __restrict__ loadings,
             float* __restrict__ out) {
    extern __shared__ __align__(16) char smem_raw[];
    float4* sdz4  = (float4*)(smem_raw + OFF_SDZ);
    float4* sfbm4 = (float4*)(smem_raw + OFF_SFBM);
    unsigned long long* sdzU = (unsigned long long*)(smem_raw + OFF_SDZ);
    unsigned long long* sfbU = (unsigned long long*)(smem_raw + OFF_SFBM);
    float* ss2   = (float*)(smem_raw + OFF_SS2);
    float* s_lam = (float*)(smem_raw + OFF_LAM);
    float* s_wk  = (float*)(smem_raw + OFF_WK);
    float* s_lamL= (float*)(smem_raw + OFF_LAML);
    float* s_g   = (float*)(smem_raw + OFF_G);
    float* wtot  = (float*)(smem_raw + OFF_WTOT);

    const int tid   = threadIdx.x;
    const int lane  = tid & 31;
    const int wid   = tid >> 5;
    const int pbase = blockIdx.x * PPB;

    for (int i = tid; i < PPB * N_STEPS; i += FUSED_TPB)
        sdz4[i] = dz[(size_t)pbase * N_STEPS + i];
    if (tid < M_SOE) {
        s_lam[tid]  = d_lam[tid];
        s_wk[tid]   = d_wk[tid];
        s_lamL[tid] = d_lamL[tid];
    }
    if (tid < K0) s_g[tid] = d_g[tid];

    // ---- in-block s2 = prefix sum of g^2 (shuffle scan, 4 elems/thread) ----
    float sc0, sc1, sc2, sc3, sa0;
    {
        float4 g4 = ((const float4*)d_g)[tid];
        sc0 = g4.x * g4.x;
        sc1 = sc0 + g4.y * g4.y;
        sc2 = sc1 + g4.z * g4.z;
        sc3 = sc2 + g4.w * g4.w;
        float incl = sc3;
        #pragma unroll
        for (int o = 1; o < 32; o <<= 1) {
            float nv = __shfl_up_sync(0xffffffffu, incl, o);
            if (lane >= o) incl += nv;
        }
        sa0 = incl - sc3;                  // exclusive within warp
        if (lane == 31) wtot[wid] = incl;
    }
    __syncthreads();
    {
        float off = sa0;
        #pragma unroll
        for (int w = 0; w < 3; w++)
            if (wid > w) off += wtot[w];
        ss2[4 * tid + 0] = off + sc0;
        ss2[4 * tid + 1] = off + sc1;
        ss2[4 * tid + 2] = off + sc2;
        ss2[4 * tid + 3] = off + sc3;
    }

    // thread map for conv: chunk c = lane, channel-pair dp, path q (one warp per (dp,q))
    const int c  = lane;
    const int dp = (tid >> 5) & 1;
    const int q  = tid >> 6;
    const int tb = c * LCH;

    // delayed stream u[t] = dz[t - K0] for t in chunk, cached in regs
    unsigned long long dzc[LCH];
    #pragma unroll
    for (int i = 0; i < LCH; i++) {
        int gt = tb + i - K0;
        dzc[i] = (gt >= 0) ? sdzU[(q * N_STEPS + gt) * 2 + dp] : 0ull;
    }

    // ---- near field: exact taps g[0..7] ----
    unsigned long long F[LCH];
    {
        unsigned long long nc[K0];
        #pragma unroll
        for (int j = 0; j < K0; j++)
            nc[j] = sdzU[(q * N_STEPS + tb + K0 + j) * 2 + dp];
        #pragma unroll
        for (int i = 0; i < LCH; i++) {
            unsigned long long acc = 0ull;
            #pragma unroll
            for (int k = 0; k < K0; k++) {
                float gv = s_g[k];
                unsigned long long g2 = pack2(gv, gv);
                const int d = i - k;               // in [-7, 15]
                unsigned long long zv = (d <= 7) ? dzc[d + 8] : nc[d - 8];
                acc = fma2(g2, zv, acc);
            }
            F[i] = acc;
        }
    }

    // ---- far field: per-mode local sum -> warp shuffle weighted scan -> replay ----
    #pragma unroll 1
    for (int m = 0; m < M_SOE; m += 2) {
        float lA = s_lam[m + 0], lB = s_lam[m + 1];
        unsigned long long lamA = pack2(lA, lA);
        unsigned long long lamB = pack2(lB, lB);

        // local chunk sums
        unsigned long long SA = 0ull, SB = 0ull;
        #pragma unroll
        for (int i = 0; i < LCH; i++) {
            SA = fma2(lamA, SA, dzc[i]);
            SB = fma2(lamB, SB, dzc[i]);
        }

        // weighted inclusive scan across lanes (chunks): incl_c = sum_{c'<=c} V_c' lamL^(c-c')
        float pA = s_lamL[m + 0], pB = s_lamL[m + 1];
        unsigned long long iA = SA, iB = SB;
        #pragma unroll
        for (int o = 1; o < 32; o <<= 1) {
            unsigned long long tA = __shfl_up_sync(0xffffffffu, iA, o);
            unsigned long long tB = __shfl_up_sync(0xffffffffu, iB, o);
            tA = (lane >= o) ? tA : 0ull;
            tB = (lane >= o) ? tB : 0ull;
            unsigned long long pA2 = pack2(pA, pA);
            unsigned long long pB2 = pack2(pB, pB);
            iA = fma2(pA2, tA, iA);
            iB = fma2(pB2, tB, iB);
            pA = pA * pA;
            pB = pB * pB;
        }

        // exclusive carry-in for this chunk
        unsigned long long cA = __shfl_up_sync(0xffffffffu, iA, 1);
        unsigned long long cB = __shfl_up_sync(0xffffffffu, iB, 1);
        cA = (lane >= 1) ? cA : 0ull;
        cB = (lane >= 1) ? cB : 0ull;

        // replay with carry, accumulate w*S into F
        float wkA = s_wk[m + 0], wkB = s_wk[m + 1];
        unsigned long long wkA2 = pack2(wkA, wkA);
        unsigned long long wkB2 = pack2(wkB, wkB);
        #pragma unroll
        for (int i = 0; i < LCH; i++) {
            cA = fma2(lamA, cA, dzc[i]);
            cB = fma2(lamB, cB, dzc[i]);
            F[i] = fma2(wkA2, cA, F[i]);
            F[i] = fma2(wkB2, cB, F[i]);
        }
    }

    #pragma unroll
    for (int i = 0; i < LCH; i++)
        sfbU[(q * (NCH * 17) + c * 17 + i) * 2 + dp] = F[i];
    __syncthreads();

    // ---- phase 2: mix / exp / dF / cumsum / store (R10 form) ----
    if (tid < PH2_THREADS) {
        const int qq = tid / N_FWD;
        const int n  = tid - qq * N_FWD;
        const int p  = pbase + qq;

        const float rho = rhos[n];
        const float nu  = nus[n];
        const float sq  = sqrtf(fmaxf(1.0f - rho * rho, 0.0f));
        const float l0  = loadings[n * 3 + 0];
        const float l1  = loadings[n * 3 + 1];
        const float l2  = loadings[n * 3 + 2];
        const float vs   = d_vs[n];
        const float muDT = d_mu0[n] * DT_F;
        const float cvar = 0.5f * nu * nu * DT_F;
        const float f0   = F0[n];

        float* op = out + (size_t)p * (N_STEPS + 1) * N_FWD + n;

        float acc = f0;
        __stcs(op, f0);
        op += N_FWD;

        for (int t = 0; t < N_STEPS; t++) {
            const int cc = t >> 4, ii = t & 15;
            float4 f = sfbm4[qq * (NCH * 17) + cc * 17 + ii];
            float4 z = sdz4[qq * N_STEPS + t];
            float fbm_curve = f.x * l0 + f.y * l1 + f.z * l2;
            float fbm = rho * fbm_curve + sq * f.w;
            float wr  = z.x * l0 + z.y * l1 + z.z * l2;
            float u   = __expf(nu * fbm - cvar * ss2[t]);
            acc += muDT * (u * u) + wr * (u * vs);
            __stcs(op, acc);
            op += N_FWD;
        }
    }
}

// ---------------- launcher ----------------
extern "C" void kernel_launch(void* const* d_in, const int* in_sizes, int n_in,
                              void* d_out, int out_size) {
    const float* dz       = (const float*)d_in[0];
    const float* F0       = (const float*)d_in[1];
    const float* alphas   = (const float*)d_in[2];
    const float* rhos     = (const float*)d_in[3];
    const float* nus      = (const float*)d_in[4];
    const float* tau      = (const float*)d_in[5];
    const float* loadings = (const float*)d_in[6];
    const float* Lam      = (const float*)d_in[7];
    float* out = (float*)d_out;

    cudaFuncSetAttribute(fused_kernel,
                         cudaFuncAttributeMaxDynamicSharedMemorySize, SMEM_BYTES);

    pre_a<<<9, 64>>>(F0, alphas, tau, Lam);
    fused_kernel<<<N_PATHS / PPB, FUSED_TPB, SMEM_BYTES>>>(
        (const float4*)dz, F0, rhos, nus, loadings, out);
}